// round 7
// baseline (speedup 1.0000x reference)
#include <cuda_runtime.h>
#include <cstdint>

#define SDIM  16
#define NNODE 256
#define VDIM  64
#define EDIM  64
#define HDIM  16
#define KEDGE 255   // N-1
#define NSN   (SDIM * NNODE)   // 4096 tiles
#define GRID  512              // persistent CTAs; 8 tiles each
#define STRIDE GRID

typedef unsigned long long ull;

// per-node projections, pr stored TRANSPOSED: g_prT[s][e][n]
__device__ float g_prT[SDIM * HDIM * NNODE];
__device__ float g_psb[SDIM * NNODE * HDIM];   // psb[sn][e] = v0@we1[64:128] + be1

__device__ __forceinline__ float fast_tanh(float x) {
    // tanh(x) = 1 - 2/(e^{2x}+1); robust at +/-inf, MUFU-based, ~1e-6 rel err
    float y = __expf(2.0f * x);
    return 1.0f - __fdividef(2.0f, y + 1.0f);
}
__device__ __forceinline__ ull pack2(float a, float b) {
    ull u; asm("mov.b64 %0, {%1, %2};" : "=l"(u) : "f"(a), "f"(b)); return u;
}

// ---------------------------------------------------------------------------
// Kernel A: per-node projections (tiny). one block per (s,n), 64 threads.
// ---------------------------------------------------------------------------
__global__ void __launch_bounds__(64) proj_kernel(
    const float* __restrict__ v0,
    const float* __restrict__ we1, const float* __restrict__ be1)
{
    const int sn  = blockIdx.x;
    const int tid = threadIdx.x;
    __shared__ float vs[VDIM];

    vs[tid] = v0[(size_t)sn * VDIM + tid];
    __syncthreads();

    const int s_idx = sn >> 8;
    const int n_idx = sn & 255;
    if (tid < 16) {
        float a = 0.f;
        #pragma unroll
        for (int e = 0; e < VDIM; e++) a = fmaf(vs[e], we1[e * HDIM + tid], a);
        g_prT[(s_idx * HDIM + tid) * NNODE + n_idx] = a;
    } else if (tid < 32) {
        int j = tid - 16;
        float a = be1[j];
        #pragma unroll
        for (int e = 0; e < VDIM; e++) a = fmaf(vs[e], we1[(VDIM + e) * HDIM + j], a);
        g_psb[sn * HDIM + j] = a;
    }
}

// ---------------------------------------------------------------------------
// Persistent mega kernel: 512 CTAs x 8 tiles. Per tile (s,n):
//   - edge GEMM (natural-pair t table in smem, lane owns 1 channel,
//     h-pair-packed weights in 16 regs, f32x2 FFMA) + streaming de stores
//   - e0 row reads in a 4-deep register pipeline; refills at groups 12-15
//     prefetch the NEXT tile's rows so DRAM reads never drain
//   - node epilogue (e0 row-sum -> 2-layer MLP -> dv) overlapped with the
//     NEXT tile's tanh-table build; weights/bias hoisted out of the loop
// ---------------------------------------------------------------------------
__global__ void __launch_bounds__(256, 4) mega_kernel(
    const float* __restrict__ e0,
    const float* __restrict__ wv1, const float* __restrict__ bv1,
    const float* __restrict__ wv2, const float* __restrict__ bv2,
    const float* __restrict__ we2, const float* __restrict__ be2,
    float* __restrict__ dv_out, float* __restrict__ de_out)
{
    __shared__ union SM {
        ulonglong2 tt2[4][256];        // 16 KB tanh table (natural pairs)
        float4     part[16][17];       // 4.3 KB epilogue partials (disjoint in time)
    } sm;
    __shared__ float psb_s[HDIM];
    __shared__ float evs_s[EDIM];
    __shared__ float hv_s [HDIM];

    const int tid = threadIdx.x;
    const int w   = tid >> 5;             // warp 0..7
    const int l   = tid & 31;             // lane
    const int c4  = l & 15;               // float4 slot in 64-wide channel dim
    const int r0  = w * 2 + (l >> 4);     // 0..15: row offset within 16-row groups
    const int a   = w >> 1;               // edge slot 0..3
    const int c   = ((w & 1) << 5) + l;   // owned output channel 0..63

    // block-invariant packed weights: h-pairs for channel c (16 regs) + bias
    ull wd[8];
    #pragma unroll
    for (int m = 0; m < 8; m++)
        wd[m] = pack2(we2[(2 * m) * VDIM + c], we2[(2 * m + 1) * VDIM + c]);
    const ull B = pack2(be2[c], 0.0f);    // bias folded into accumulator init

    const size_t E0S = (size_t)KEDGE * EDIM / 4;   // float4 per tile
    int sn = blockIdx.x;
    const float4* e0p = reinterpret_cast<const float4*>(e0) + (size_t)sn * E0S;

    // ---- prologue for tile 0: psb, tanh table, buf rows 0..63 ----
    if (tid < 4)
        reinterpret_cast<float4*>(psb_s)[tid] =
            reinterpret_cast<const float4*>(g_psb + sn * HDIM)[tid];
    __syncthreads();

    if (tid < KEDGE) {
        const int i = sn & 255;
        const int j = tid + (tid >= i);
        const float* prb = g_prT + (sn >> 8) * HDIM * NNODE + j;
        #pragma unroll
        for (int m = 0; m < 4; m++) {
            float t0 = fast_tanh(__ldg(prb + (4 * m    ) * NNODE) + psb_s[4 * m    ]);
            float t1 = fast_tanh(__ldg(prb + (4 * m + 1) * NNODE) + psb_s[4 * m + 1]);
            float t2 = fast_tanh(__ldg(prb + (4 * m + 2) * NNODE) + psb_s[4 * m + 2]);
            float t3 = fast_tanh(__ldg(prb + (4 * m + 3) * NNODE) + psb_s[4 * m + 3]);
            sm.tt2[m][tid] = make_ulonglong2(pack2(t0, t1), pack2(t2, t3));
        }
    }
    float4 buf[4];
    #pragma unroll
    for (int u = 0; u < 4; u++)
        buf[u] = __ldcs(&e0p[(u * 16 + r0) * 16 + c4]);
    __syncthreads();                       // table ready

#define EDGE_ITER(K) do {                                                      \
        const int k_ = (K);                                                    \
        if (k_ < KEDGE) {                                                      \
            ull A0 = B, A1 = 0;                                                \
            _Pragma("unroll")                                                  \
            for (int m = 0; m < 4; m++) {                                      \
                ulonglong2 tp = sm.tt2[m][k_];          /* broadcast LDS.128 */\
                asm("fma.rn.f32x2 %0, %1, %2, %0;" : "+l"(A0) : "l"(wd[2*m  ]), "l"(tp.x)); \
                asm("fma.rn.f32x2 %0, %1, %2, %0;" : "+l"(A1) : "l"(wd[2*m+1]), "l"(tp.y)); \
            }                                                                  \
            asm("add.rn.f32x2 %0, %0, %1;" : "+l"(A0) : "l"(A1));              \
            float lo_, hi_;                                                    \
            asm("mov.b64 {%0, %1}, %2;" : "=f"(lo_), "=f"(hi_) : "l"(A0));     \
            __stcs(outp + (size_t)k_ * VDIM, lo_ + hi_);                       \
        }                                                                      \
    } while (0)

    // ==================== persistent tile loop ====================
    #pragma unroll 1
    for (int it = 0; it < NSN / STRIDE; it++) {
        const bool more = (it < NSN / STRIDE - 1);
        const float4* e0pn = e0p + (size_t)STRIDE * E0S;   // next tile
        float* outp = de_out + (size_t)sn * KEDGE * VDIM + c;
        ull accA = 0, accB = 0;

        // ---- main loop: 16 groups x (4 edge iters + consume + refill) ----
        #pragma unroll 1
        for (int gb = 0; gb < 16; gb += 4) {
            #pragma unroll
            for (int u = 0; u < 4; u++) {
                const int g = gb + u;
                EDGE_ITER(16 * g      + a);
                EDGE_ITER(16 * g + 4  + a);
                EDGE_ITER(16 * g + 8  + a);
                EDGE_ITER(16 * g + 12 + a);
                {
                    float4 v = buf[u];
                    const int r = g * 16 + r0;
                    if (r < KEDGE) {
                        ull va = pack2(v.x, v.y), vb = pack2(v.z, v.w);
                        asm("add.rn.f32x2 %0, %0, %1;" : "+l"(accA) : "l"(va));
                        asm("add.rn.f32x2 %0, %0, %1;" : "+l"(accB) : "l"(vb));
                    }
                    if (g < 12) {
                        const int rn = r + 64;
                        if (rn < KEDGE) buf[u] = __ldcs(&e0p[rn * 16 + c4]);
                    } else if (more) {
                        // prefetch next tile's rows 0..63 (keeps reads in flight)
                        buf[u] = __ldcs(&e0pn[((g - 12) * 16 + r0) * 16 + c4]);
                    }
                }
            }
        }

        // ---- epilogue (node MLP) overlapped with next tile's table build ----
        float4 acc4;
        asm("mov.b64 {%0, %1}, %2;" : "=f"(acc4.x), "=f"(acc4.y) : "l"(accA));
        asm("mov.b64 {%0, %1}, %2;" : "=f"(acc4.z), "=f"(acc4.w) : "l"(accB));

        __syncthreads();                   // tt2 reads done; part may reuse it
        sm.part[r0][c4] = acc4;
        if (more && tid < 4)               // prefetch next psb (read 2 syncs later)
            reinterpret_cast<float4*>(psb_s)[tid] =
                reinterpret_cast<const float4*>(g_psb + (sn + STRIDE) * HDIM)[tid];
        __syncthreads();

        if (tid < 16) {
            float4 p4 = sm.part[0][tid];
            #pragma unroll
            for (int g = 1; g < 16; g++) {
                float4 p = sm.part[g][tid];
                p4.x += p.x; p4.y += p.y; p4.z += p.z; p4.w += p.w;
            }
            reinterpret_cast<float4*>(evs_s)[tid] = p4;
        }
        __syncthreads();                   // part reads done; tt2 rebuild safe

        if (tid < 16) {
            float v = bv1[tid];
            #pragma unroll
            for (int e = 0; e < EDIM; e++) v = fmaf(evs_s[e], wv1[e * HDIM + tid], v);
            hv_s[tid] = fast_tanh(v);
        }
        if (more && tid < KEDGE) {         // build next tile's tanh table
            const int i2 = (sn + STRIDE) & 255;
            const int j2 = tid + (tid >= i2);
            const float* prb = g_prT + ((sn + STRIDE) >> 8) * HDIM * NNODE + j2;
            #pragma unroll
            for (int m = 0; m < 4; m++) {
                float t0 = fast_tanh(__ldg(prb + (4 * m    ) * NNODE) + psb_s[4 * m    ]);
                float t1 = fast_tanh(__ldg(prb + (4 * m + 1) * NNODE) + psb_s[4 * m + 1]);
                float t2 = fast_tanh(__ldg(prb + (4 * m + 2) * NNODE) + psb_s[4 * m + 2]);
                float t3 = fast_tanh(__ldg(prb + (4 * m + 3) * NNODE) + psb_s[4 * m + 3]);
                sm.tt2[m][tid] = make_ulonglong2(pack2(t0, t1), pack2(t2, t3));
            }
        }
        __syncthreads();                   // hv + next table ready

        if (tid < VDIM) {
            float v = bv2[tid];
            #pragma unroll
            for (int j = 0; j < HDIM; j++) v = fmaf(hv_s[j], wv2[j * VDIM + tid], v);
            dv_out[(size_t)sn * VDIM + tid] = v;
        }

        sn += STRIDE;
        e0p = e0pn;
    }
#undef EDGE_ITER
}

// ---------------------------------------------------------------------------
// inputs (metadata order): t, v0, e0, wv1, bv1, wv2, bv2, we1, be1, we2, be2,
//                          recv_idx, send_idx (idx arrays unused: analytic)
// output: dv (S,N,V) followed by de (S,N,N-1,E)
// ---------------------------------------------------------------------------
extern "C" void kernel_launch(void* const* d_in, const int* in_sizes, int n_in,
                              void* d_out, int out_size)
{
    const float* v0  = (const float*)d_in[1];
    const float* e0  = (const float*)d_in[2];
    const float* wv1 = (const float*)d_in[3];
    const float* bv1 = (const float*)d_in[4];
    const float* wv2 = (const float*)d_in[5];
    const float* bv2 = (const float*)d_in[6];
    const float* we1 = (const float*)d_in[7];
    const float* be1 = (const float*)d_in[8];
    const float* we2 = (const float*)d_in[9];
    const float* be2 = (const float*)d_in[10];

    float* dv_out = (float*)d_out;
    float* de_out = dv_out + (size_t)SDIM * NNODE * VDIM;

    proj_kernel<<<SDIM * NNODE, 64>>>(v0, we1, be1);
    mega_kernel<<<GRID, 256>>>(e0, wv1, bv1, wv2, bv2, we2, be2,
                               dv_out, de_out);
}

// round 8
// speedup vs baseline: 1.1567x; 1.1567x over previous
#include <cuda_runtime.h>
#include <cstdint>

#define SDIM  16
#define NNODE 256
#define VDIM  64
#define EDIM  64
#define HDIM  16
#define KEDGE 255   // N-1

typedef unsigned long long ull;

// per-node projections, pr stored TRANSPOSED: g_prT[s][e][n]
__device__ float g_prT[SDIM * HDIM * NNODE];
__device__ float g_psb[SDIM * NNODE * HDIM];   // psb[sn][e] = v0@we1[64:128] + be1

__device__ __forceinline__ float fast_tanh(float x) {
    // tanh(x) = 1 - 2/(e^{2x}+1); robust at +/-inf, MUFU-based, ~1e-6 rel err
    float y = __expf(2.0f * x);
    return 1.0f - __fdividef(2.0f, y + 1.0f);
}
__device__ __forceinline__ ull pack2(float a, float b) {
    ull u; asm("mov.b64 %0, {%1, %2};" : "=l"(u) : "f"(a), "f"(b)); return u;
}

// ---------------------------------------------------------------------------
// Kernel A: per-node projections (tiny). one block per (s,n), 64 threads.
// ---------------------------------------------------------------------------
__global__ void __launch_bounds__(64) proj_kernel(
    const float* __restrict__ v0,
    const float* __restrict__ we1, const float* __restrict__ be1)
{
    const int sn  = blockIdx.x;
    const int tid = threadIdx.x;
    __shared__ float vs[VDIM];

    vs[tid] = v0[(size_t)sn * VDIM + tid];
    __syncthreads();

    const int s_idx = sn >> 8;
    const int n_idx = sn & 255;
    if (tid < 16) {
        float a = 0.f;
        #pragma unroll
        for (int e = 0; e < VDIM; e++) a = fmaf(vs[e], we1[e * HDIM + tid], a);
        g_prT[(s_idx * HDIM + tid) * NNODE + n_idx] = a;
    } else if (tid < 32) {
        int j = tid - 16;
        float a = be1[j];
        #pragma unroll
        for (int e = 0; e < VDIM; e++) a = fmaf(vs[e], we1[(VDIM + e) * HDIM + j], a);
        g_psb[sn * HDIM + j] = a;
    }
}

// ---------------------------------------------------------------------------
// Mega kernel (R6 structure, R=2 channels/lane): one block per (s,n), 3 CTAs/SM.
//  Natural-pair tanh table (16KB). Lane owns channels 2l,2l+1 -> each tpair
//  LDS feeds 4 FFMA2 (t reused across both channels); ONE warp per edge.
//  LDS per tile halves vs R6 (1024), STG.64 stores, FFMA2 count unchanged.
//  e0 reads pipelined in a 4-deep register buffer (1 LDG per 2 edge iters).
// ---------------------------------------------------------------------------
__global__ void __launch_bounds__(256, 3) mega_kernel(
    const float* __restrict__ e0,
    const float* __restrict__ wv1, const float* __restrict__ bv1,
    const float* __restrict__ wv2, const float* __restrict__ bv2,
    const float* __restrict__ we2, const float* __restrict__ be2,
    float* __restrict__ dv_out, float* __restrict__ de_out)
{
    __shared__ union SM {
        ulonglong2 tt2[4][256];                                      // 16 KB
        struct { float4 part[16][17]; float evs[EDIM]; float hv[HDIM]; } node;
    } sm;
    __shared__ float psb_s[HDIM];

    const int sn  = blockIdx.x;           // s*256 + n  (n is also edge-row i)
    const int s   = sn >> 8;
    const int i   = sn & 255;
    const int tid = threadIdx.x;
    const int w   = tid >> 5;             // warp 0..7 == edge slot
    const int l   = tid & 31;             // lane
    const int c4  = l & 15;               // float4 slot in 64-wide channel dim
    const int r0  = w * 2 + (l >> 4);     // 0..15: row offset within 16-row groups
    const int c0  = l << 1;               // owned channels c0, c0+1

    const float4* e0p = reinterpret_cast<const float4*>(e0)
                      + (size_t)sn * (KEDGE * EDIM / 4);

    // prologue: fill 4-deep circular buffer (rows 0..63, all valid)
    float4 buf[4];
    #pragma unroll
    for (int u = 0; u < 4; u++)
        buf[u] = __ldcs(&e0p[(u * 16 + r0) * 16 + c4]);

    if (tid < 4)
        reinterpret_cast<float4*>(psb_s)[tid] =
            reinterpret_cast<const float4*>(g_psb + sn * HDIM)[tid];

    // lane weights: h-pair packed for channels c0, c0+1 -> 16 ull (32 regs)
    ull wa[8], wb[8];
    #pragma unroll
    for (int m = 0; m < 8; m++) {
        wa[m] = pack2(we2[(2 * m) * VDIM + c0    ], we2[(2 * m + 1) * VDIM + c0    ]);
        wb[m] = pack2(we2[(2 * m) * VDIM + c0 + 1], we2[(2 * m + 1) * VDIM + c0 + 1]);
    }
    const ull Ba = pack2(be2[c0    ], 0.0f);   // bias folded into accum init
    const ull Bb = pack2(be2[c0 + 1], 0.0f);
    __syncthreads();                       // psb_s visible

    // --- tanh table: thread k computes t[k][0..15] in natural order ---
    if (tid < KEDGE) {
        const int j = tid + (tid >= i);    // skip diagonal
        const float* prb = g_prT + s * HDIM * NNODE + j;
        #pragma unroll
        for (int m = 0; m < 4; m++) {
            float t0 = fast_tanh(__ldg(prb + (4 * m    ) * NNODE) + psb_s[4 * m    ]);
            float t1 = fast_tanh(__ldg(prb + (4 * m + 1) * NNODE) + psb_s[4 * m + 1]);
            float t2 = fast_tanh(__ldg(prb + (4 * m + 2) * NNODE) + psb_s[4 * m + 2]);
            float t3 = fast_tanh(__ldg(prb + (4 * m + 3) * NNODE) + psb_s[4 * m + 3]);
            sm.tt2[m][tid] = make_ulonglong2(pack2(t0, t1), pack2(t2, t3));
        }
    }
    __syncthreads();                       // table ready

    ull accA = 0, accB = 0;                // packed e0 partial sums
    float* outp = de_out + (size_t)sn * KEDGE * VDIM + c0;

#define EDGE_ITER(K) do {                                                      \
        const int k_ = (K);                                                    \
        if (k_ < KEDGE) {                                                      \
            ull Aa0 = Ba, Aa1 = 0, Ab0 = Bb, Ab1 = 0;                          \
            _Pragma("unroll")                                                  \
            for (int m = 0; m < 4; m++) {                                      \
                ulonglong2 tp = sm.tt2[m][k_];          /* broadcast LDS.128 */\
                asm("fma.rn.f32x2 %0, %1, %2, %0;" : "+l"(Aa0) : "l"(wa[2*m  ]), "l"(tp.x)); \
                asm("fma.rn.f32x2 %0, %1, %2, %0;" : "+l"(Ab0) : "l"(wb[2*m  ]), "l"(tp.x)); \
                asm("fma.rn.f32x2 %0, %1, %2, %0;" : "+l"(Aa1) : "l"(wa[2*m+1]), "l"(tp.y)); \
                asm("fma.rn.f32x2 %0, %1, %2, %0;" : "+l"(Ab1) : "l"(wb[2*m+1]), "l"(tp.y)); \
            }                                                                  \
            asm("add.rn.f32x2 %0, %0, %1;" : "+l"(Aa0) : "l"(Aa1));            \
            asm("add.rn.f32x2 %0, %0, %1;" : "+l"(Ab0) : "l"(Ab1));            \
            float a_lo, a_hi, b_lo, b_hi;                                      \
            asm("mov.b64 {%0, %1}, %2;" : "=f"(a_lo), "=f"(a_hi) : "l"(Aa0));  \
            asm("mov.b64 {%0, %1}, %2;" : "=f"(b_lo), "=f"(b_hi) : "l"(Ab0));  \
            float2 o_ = make_float2(a_lo + a_hi, b_lo + b_hi);                 \
            __stcs(reinterpret_cast<float2*>(outp + (size_t)k_ * VDIM), o_);   \
        }                                                                      \
    } while (0)

    // --- pipelined main loop: 16 groups; per group 2 edge iters + 1 LDG ---
    #pragma unroll 1
    for (int gb = 0; gb < 16; gb += 4) {
        #pragma unroll
        for (int u = 0; u < 4; u++) {
            const int g = gb + u;
            EDGE_ITER(16 * g     + w);
            EDGE_ITER(16 * g + 8 + w);
            // consume buf[u] (row group g), then refill with group g+4
            {
                float4 v = buf[u];
                const int r = g * 16 + r0;
                if (r < KEDGE) {
                    ull va = pack2(v.x, v.y), vb = pack2(v.z, v.w);
                    asm("add.rn.f32x2 %0, %0, %1;" : "+l"(accA) : "l"(va));
                    asm("add.rn.f32x2 %0, %0, %1;" : "+l"(accB) : "l"(vb));
                }
                const int rn = r + 64;
                if (rn < KEDGE) buf[u] = __ldcs(&e0p[rn * 16 + c4]);
            }
        }
    }
#undef EDGE_ITER

    // --- node epilogue: reduce partials (reuse smem), tiny MLPs ---
    float4 acc;
    asm("mov.b64 {%0, %1}, %2;" : "=f"(acc.x), "=f"(acc.y) : "l"(accA));
    asm("mov.b64 {%0, %1}, %2;" : "=f"(acc.z), "=f"(acc.w) : "l"(accB));

    __syncthreads();                       // everyone done reading tt2
    sm.node.part[r0][c4] = acc;            // 16 owners x 16 c4 slots
    __syncthreads();

    if (tid < 16) {
        float4 p4 = sm.node.part[0][tid];
        #pragma unroll
        for (int g = 1; g < 16; g++) {
            float4 p = sm.node.part[g][tid];
            p4.x += p.x; p4.y += p.y; p4.z += p.z; p4.w += p.w;
        }
        reinterpret_cast<float4*>(sm.node.evs)[tid] = p4;
    }
    __syncthreads();

    if (tid < 16) {
        float v = bv1[tid];
        #pragma unroll
        for (int e = 0; e < EDIM; e++) v = fmaf(sm.node.evs[e], wv1[e * HDIM + tid], v);
        sm.node.hv[tid] = fast_tanh(v);
    }
    __syncthreads();

    if (tid < VDIM) {
        float v = bv2[tid];
        #pragma unroll
        for (int j = 0; j < HDIM; j++) v = fmaf(sm.node.hv[j], wv2[j * VDIM + tid], v);
        dv_out[(size_t)sn * VDIM + tid] = v;
    }
}

// ---------------------------------------------------------------------------
// inputs (metadata order): t, v0, e0, wv1, bv1, wv2, bv2, we1, be1, we2, be2,
//                          recv_idx, send_idx (idx arrays unused: analytic)
// output: dv (S,N,V) followed by de (S,N,N-1,E)
// ---------------------------------------------------------------------------
extern "C" void kernel_launch(void* const* d_in, const int* in_sizes, int n_in,
                              void* d_out, int out_size)
{
    const float* v0  = (const float*)d_in[1];
    const float* e0  = (const float*)d_in[2];
    const float* wv1 = (const float*)d_in[3];
    const float* bv1 = (const float*)d_in[4];
    const float* wv2 = (const float*)d_in[5];
    const float* bv2 = (const float*)d_in[6];
    const float* we1 = (const float*)d_in[7];
    const float* be1 = (const float*)d_in[8];
    const float* we2 = (const float*)d_in[9];
    const float* be2 = (const float*)d_in[10];

    float* dv_out = (float*)d_out;
    float* de_out = dv_out + (size_t)SDIM * NNODE * VDIM;

    proj_kernel<<<SDIM * NNODE, 64>>>(v0, we1, be1);
    mega_kernel<<<SDIM * NNODE, 256>>>(e0, wv1, bv1, wv2, bv2, we2, be2,
                                       dv_out, de_out);
}

// round 9
// speedup vs baseline: 1.1756x; 1.0164x over previous
#include <cuda_runtime.h>
#include <cstdint>

#define SDIM  16
#define NNODE 256
#define VDIM  64
#define EDIM  64
#define HDIM  16
#define KEDGE 255   // N-1
#define NSN   (SDIM * NNODE)

typedef unsigned long long ull;

// per-node projections, pr stored TRANSPOSED: g_prT[s][e][n]
__device__ float g_prT[SDIM * HDIM * NNODE];
__device__ float g_psb[SDIM * NNODE * HDIM];   // psb[sn][e] = v0@we1[64:128] + be1

__device__ __forceinline__ float fast_tanh(float x) {
    // tanh(x) = 1 - 2/(e^{2x}+1); robust at +/-inf, MUFU-based, ~1e-6 rel err
    float y = __expf(2.0f * x);
    return 1.0f - __fdividef(2.0f, y + 1.0f);
}
__device__ __forceinline__ ull pack2(float a, float b) {
    ull u; asm("mov.b64 %0, {%1, %2};" : "=l"(u) : "f"(a), "f"(b)); return u;
}

// ---------------------------------------------------------------------------
// Kernel A: per-node projections. 256 blocks x 256 threads, 16 nodes/block.
// thread (node_local = tid>>4, h = tid&15) computes pr and psb for its node.
// ---------------------------------------------------------------------------
__global__ void __launch_bounds__(256) proj_kernel(
    const float* __restrict__ v0,
    const float* __restrict__ we1, const float* __restrict__ be1)
{
    const int tid = threadIdx.x;
    const int nl  = tid >> 4;             // node 0..15 within block
    const int h   = tid & 15;             // output h-dim
    const int sn  = blockIdx.x * 16 + nl;

    __shared__ float vs[16][VDIM];

    // coalesced stage: 256 threads x float4 = 16 rows x 64 floats
    {
        const float4* src = reinterpret_cast<const float4*>(v0)
                          + (size_t)blockIdx.x * 16 * 16;
        reinterpret_cast<float4*>(&vs[0][0])[tid] = src[tid];
    }
    __syncthreads();

    float pr  = 0.f;
    float psb = be1[h];
    #pragma unroll
    for (int e = 0; e < VDIM; e++) {
        float v = vs[nl][e];
        pr  = fmaf(v, we1[e * HDIM + h], pr);
        psb = fmaf(v, we1[(VDIM + e) * HDIM + h], psb);
    }
    const int s_idx = sn >> 8;
    const int n_idx = sn & 255;
    g_prT[(s_idx * HDIM + h) * NNODE + n_idx] = pr;   // transposed
    g_psb[sn * HDIM + h] = psb;
}

// ---------------------------------------------------------------------------
// Mega kernel (R8 body + L2 prefetch): one block per (s,n), 3 CTAs/SM.
//  Natural-pair tanh table (16KB). Lane owns channels 2l,2l+1; one warp/edge.
//  e0 reads: 4-deep register pipeline; each refill also issues a
//  prefetch.global.L2 for the row 4 groups (+16KB) ahead, so the later LDG
//  hits L2 (~250cyc) instead of DRAM (~600cyc). Prefetch is no-reg,
//  fire-and-forget -> DRAM read stream decoupled from warp stalls.
// ---------------------------------------------------------------------------
__global__ void __launch_bounds__(256, 3) mega_kernel(
    const float* __restrict__ e0,
    const float* __restrict__ wv1, const float* __restrict__ bv1,
    const float* __restrict__ wv2, const float* __restrict__ bv2,
    const float* __restrict__ we2, const float* __restrict__ be2,
    float* __restrict__ dv_out, float* __restrict__ de_out)
{
    __shared__ union SM {
        ulonglong2 tt2[4][256];                                      // 16 KB
        struct { float4 part[16][17]; float evs[EDIM]; float hv[HDIM]; } node;
    } sm;
    __shared__ float psb_s[HDIM];

    const int sn  = blockIdx.x;           // s*256 + n  (n is also edge-row i)
    const int s   = sn >> 8;
    const int i   = sn & 255;
    const int tid = threadIdx.x;
    const int w   = tid >> 5;             // warp 0..7 == edge slot
    const int l   = tid & 31;             // lane
    const int c4  = l & 15;               // float4 slot in 64-wide channel dim
    const int r0  = w * 2 + (l >> 4);     // 0..15: row offset within 16-row groups
    const int c0  = l << 1;               // owned channels c0, c0+1

    // prefetch predicate: 2 lanes per row cover both 128B lines of a 256B row;
    // last tile must not prefetch past the end of e0
    const bool pf = ((c4 & 7) == 0) && (sn != NSN - 1);

    const float4* e0p = reinterpret_cast<const float4*>(e0)
                      + (size_t)sn * (KEDGE * EDIM / 4);

    // prologue: fill 4-deep circular buffer (rows 0..63) + prefetch rows 64..127
    float4 buf[4];
    #pragma unroll
    for (int u = 0; u < 4; u++) {
        const float4* p = &e0p[(u * 16 + r0) * 16 + c4];
        buf[u] = __ldcs(p);
        if (pf) asm volatile("prefetch.global.L2 [%0];" :: "l"(p + 1024));
    }

    if (tid < 4)
        reinterpret_cast<float4*>(psb_s)[tid] =
            reinterpret_cast<const float4*>(g_psb + sn * HDIM)[tid];

    // lane weights: h-pair packed for channels c0, c0+1 -> 16 ull (32 regs)
    ull wa[8], wb[8];
    #pragma unroll
    for (int m = 0; m < 8; m++) {
        wa[m] = pack2(we2[(2 * m) * VDIM + c0    ], we2[(2 * m + 1) * VDIM + c0    ]);
        wb[m] = pack2(we2[(2 * m) * VDIM + c0 + 1], we2[(2 * m + 1) * VDIM + c0 + 1]);
    }
    const ull Ba = pack2(be2[c0    ], 0.0f);   // bias folded into accum init
    const ull Bb = pack2(be2[c0 + 1], 0.0f);
    __syncthreads();                       // psb_s visible

    // --- tanh table: thread k computes t[k][0..15] in natural order ---
    if (tid < KEDGE) {
        const int j = tid + (tid >= i);    // skip diagonal
        const float* prb = g_prT + s * HDIM * NNODE + j;
        #pragma unroll
        for (int m = 0; m < 4; m++) {
            float t0 = fast_tanh(__ldg(prb + (4 * m    ) * NNODE) + psb_s[4 * m    ]);
            float t1 = fast_tanh(__ldg(prb + (4 * m + 1) * NNODE) + psb_s[4 * m + 1]);
            float t2 = fast_tanh(__ldg(prb + (4 * m + 2) * NNODE) + psb_s[4 * m + 2]);
            float t3 = fast_tanh(__ldg(prb + (4 * m + 3) * NNODE) + psb_s[4 * m + 3]);
            sm.tt2[m][tid] = make_ulonglong2(pack2(t0, t1), pack2(t2, t3));
        }
    }
    __syncthreads();                       // table ready

    ull accA = 0, accB = 0;                // packed e0 partial sums
    float* outp = de_out + (size_t)sn * KEDGE * VDIM + c0;

#define EDGE_ITER(K) do {                                                      \
        const int k_ = (K);                                                    \
        if (k_ < KEDGE) {                                                      \
            ull Aa0 = Ba, Aa1 = 0, Ab0 = Bb, Ab1 = 0;                          \
            _Pragma("unroll")                                                  \
            for (int m = 0; m < 4; m++) {                                      \
                ulonglong2 tp = sm.tt2[m][k_];          /* broadcast LDS.128 */\
                asm("fma.rn.f32x2 %0, %1, %2, %0;" : "+l"(Aa0) : "l"(wa[2*m  ]), "l"(tp.x)); \
                asm("fma.rn.f32x2 %0, %1, %2, %0;" : "+l"(Ab0) : "l"(wb[2*m  ]), "l"(tp.x)); \
                asm("fma.rn.f32x2 %0, %1, %2, %0;" : "+l"(Aa1) : "l"(wa[2*m+1]), "l"(tp.y)); \
                asm("fma.rn.f32x2 %0, %1, %2, %0;" : "+l"(Ab1) : "l"(wb[2*m+1]), "l"(tp.y)); \
            }                                                                  \
            asm("add.rn.f32x2 %0, %0, %1;" : "+l"(Aa0) : "l"(Aa1));            \
            asm("add.rn.f32x2 %0, %0, %1;" : "+l"(Ab0) : "l"(Ab1));            \
            float a_lo, a_hi, b_lo, b_hi;                                      \
            asm("mov.b64 {%0, %1}, %2;" : "=f"(a_lo), "=f"(a_hi) : "l"(Aa0));  \
            asm("mov.b64 {%0, %1}, %2;" : "=f"(b_lo), "=f"(b_hi) : "l"(Ab0));  \
            float2 o_ = make_float2(a_lo + a_hi, b_lo + b_hi);                 \
            __stcs(reinterpret_cast<float2*>(outp + (size_t)k_ * VDIM), o_);   \
        }                                                                      \
    } while (0)

    // --- pipelined main loop: 16 groups; per group 2 edge iters + 1 LDG
    //     + 1 prefetch (row +64 ahead of the LDG) ---
    #pragma unroll 1
    for (int gb = 0; gb < 16; gb += 4) {
        #pragma unroll
        for (int u = 0; u < 4; u++) {
            const int g = gb + u;
            EDGE_ITER(16 * g     + w);
            EDGE_ITER(16 * g + 8 + w);
            // consume buf[u] (row group g), then refill with group g+4
            {
                float4 v = buf[u];
                const int r = g * 16 + r0;
                if (r < KEDGE) {
                    ull va = pack2(v.x, v.y), vb = pack2(v.z, v.w);
                    asm("add.rn.f32x2 %0, %0, %1;" : "+l"(accA) : "l"(va));
                    asm("add.rn.f32x2 %0, %0, %1;" : "+l"(accB) : "l"(vb));
                }
                const int rn = r + 64;
                const float4* p = &e0p[rn * 16 + c4];
                if (rn < KEDGE) buf[u] = __ldcs(p);
                // prefetch row rn+64 (may spill into next tile: still useful)
                if (pf) asm volatile("prefetch.global.L2 [%0];" :: "l"(p + 1024));
            }
        }
    }
#undef EDGE_ITER

    // --- node epilogue: reduce partials (reuse smem), tiny MLPs ---
    float4 acc;
    asm("mov.b64 {%0, %1}, %2;" : "=f"(acc.x), "=f"(acc.y) : "l"(accA));
    asm("mov.b64 {%0, %1}, %2;" : "=f"(acc.z), "=f"(acc.w) : "l"(accB));

    __syncthreads();                       // everyone done reading tt2
    sm.node.part[r0][c4] = acc;            // 16 owners x 16 c4 slots
    __syncthreads();

    if (tid < 16) {
        float4 p4 = sm.node.part[0][tid];
        #pragma unroll
        for (int g = 1; g < 16; g++) {
            float4 p = sm.node.part[g][tid];
            p4.x += p.x; p4.y += p.y; p4.z += p.z; p4.w += p.w;
        }
        reinterpret_cast<float4*>(sm.node.evs)[tid] = p4;
    }
    __syncthreads();

    if (tid < 16) {
        float v = bv1[tid];
        #pragma unroll
        for (int e = 0; e < EDIM; e++) v = fmaf(sm.node.evs[e], wv1[e * HDIM + tid], v);
        sm.node.hv[tid] = fast_tanh(v);
    }
    __syncthreads();

    if (tid < VDIM) {
        float v = bv2[tid];
        #pragma unroll
        for (int j = 0; j < HDIM; j++) v = fmaf(sm.node.hv[j], wv2[j * VDIM + tid], v);
        dv_out[(size_t)sn * VDIM + tid] = v;
    }
}

// ---------------------------------------------------------------------------
// inputs (metadata order): t, v0, e0, wv1, bv1, wv2, bv2, we1, be1, we2, be2,
//                          recv_idx, send_idx (idx arrays unused: analytic)
// output: dv (S,N,V) followed by de (S,N,N-1,E)
// ---------------------------------------------------------------------------
extern "C" void kernel_launch(void* const* d_in, const int* in_sizes, int n_in,
                              void* d_out, int out_size)
{
    const float* v0  = (const float*)d_in[1];
    const float* e0  = (const float*)d_in[2];
    const float* wv1 = (const float*)d_in[3];
    const float* bv1 = (const float*)d_in[4];
    const float* wv2 = (const float*)d_in[5];
    const float* bv2 = (const float*)d_in[6];
    const float* we1 = (const float*)d_in[7];
    const float* be1 = (const float*)d_in[8];
    const float* we2 = (const float*)d_in[9];
    const float* be2 = (const float*)d_in[10];

    float* dv_out = (float*)d_out;
    float* de_out = dv_out + (size_t)SDIM * NNODE * VDIM;

    proj_kernel<<<NSN / 16, 256>>>(v0, we1, be1);
    mega_kernel<<<NSN, 256>>>(e0, wv1, bv1, wv2, bv2, we2, be2,
                              dv_out, de_out);
}